// round 11
// baseline (speedup 1.0000x reference)
#include <cuda_runtime.h>
#include <cuda_fp16.h>
#include <cuda_fp8.h>
#include <cstdint>

// ---------------- problem dims ----------------
#define N_ROWS 32768
#define M_CENT 4096
#define D_DIM  32

#define BLOCK     256                    // 8 warps, warp = 16 rows
#define ROWS_CTA  128
#define NTILE     128                    // centers per tile (= one split)
#define NSPLIT    32
#define NRB       (N_ROWS / ROWS_CTA)    // 256 row blocks
#define TOTTILES  (NRB * NSPLIT)         // 8192 work tiles
#define NCTAS     592                    // 148 SMs x 4 CTAs -> single wave
#define NGRP      (NTILE / 8)
#define BSTRIDE   144                    // 128B payload + 16B pad

#define SLOT_B    (NTILE * BSTRIDE)      // 18432
#define SLOT_YA   (NTILE * 8)            // 1024
#define SLOT      (SLOT_B + SLOT_YA)     // 19456
#define SMEM_TOT  (2 * SLOT)             // 38912 -> 4 CTAs/SM

#define INV_SCALE 4.8828125e-4f          // 2^-11

// ---------------- device scratch ----------------
// per center, 128 B: [0,64) fp16 yh ; [64,128) fp8 blocks:
//   for q=0..3: at 64+16q: { e4(y[4q..4q+3]), e4(y[4q+16..19]), e4(2048*yl[4q..]), e4(2048*yl[4q+16..]) }
__device__ uint8_t g_B[M_CENT * 128];
__device__ float2  g_ya[M_CENT];            // { -0.5*||ys||^2 , alpha }
__device__ float   g_part[NSPLIT * N_ROWS];

// ---------------- helpers ----------------
__device__ __forceinline__ uint32_t smem_u32(const void* p) {
    uint32_t a;
    asm("{ .reg .u64 t; cvta.to.shared.u64 t, %1; cvt.u32.u64 %0, t; }" : "=r"(a) : "l"(p));
    return a;
}
__device__ __forceinline__ float ex2f(float x) {
    float r; asm("ex2.approx.f32 %0, %1;" : "=f"(r) : "f"(x)); return r;
}
__device__ __forceinline__ void cp16(uint32_t dst, const void* src) {
    asm volatile("cp.async.cg.shared.global [%0], [%1], 16;" :: "r"(dst), "l"(src));
}
__device__ __forceinline__ void cp_commit() {
    asm volatile("cp.async.commit_group;" ::: "memory");
}
template <int N>
__device__ __forceinline__ void cp_wait() {
    asm volatile("cp.async.wait_group %0;" :: "n"(N) : "memory");
}
__device__ __forceinline__ void ldmx4(uint32_t* r, uint32_t addr) {
    asm volatile("ldmatrix.sync.aligned.m8n8.x4.shared.b16 {%0,%1,%2,%3}, [%4];"
                 : "=r"(r[0]), "=r"(r[1]), "=r"(r[2]), "=r"(r[3]) : "r"(addr));
}
// fp16 m16n8k16: D = A*B + C
__device__ __forceinline__ void mma_f16_c(float* d, const uint32_t* a, uint32_t b0, uint32_t b1,
                                          float c0, float c1, float c2, float c3) {
    asm volatile(
        "mma.sync.aligned.m16n8k16.row.col.f32.f16.f16.f32 "
        "{%0,%1,%2,%3}, {%4,%5,%6,%7}, {%8,%9}, {%10,%11,%12,%13};"
        : "=f"(d[0]), "=f"(d[1]), "=f"(d[2]), "=f"(d[3])
        : "r"(a[0]), "r"(a[1]), "r"(a[2]), "r"(a[3]), "r"(b0), "r"(b1),
          "f"(c0), "f"(c1), "f"(c2), "f"(c3));
}
__device__ __forceinline__ void mma_f16(float* d, const uint32_t* a, uint32_t b0, uint32_t b1) {
    asm volatile(
        "mma.sync.aligned.m16n8k16.row.col.f32.f16.f16.f32 "
        "{%0,%1,%2,%3}, {%4,%5,%6,%7}, {%8,%9}, {%0,%1,%2,%3};"
        : "+f"(d[0]), "+f"(d[1]), "+f"(d[2]), "+f"(d[3])
        : "r"(a[0]), "r"(a[1]), "r"(a[2]), "r"(a[3]), "r"(b0), "r"(b1));
}
// fp8 e4m3 m16n8k32: D = A*B + C(zero) / + D
__device__ __forceinline__ void mma_e4_z(float* d, const uint32_t* a, uint32_t b0, uint32_t b1) {
    asm volatile(
        "mma.sync.aligned.m16n8k32.row.col.f32.e4m3.e4m3.f32 "
        "{%0,%1,%2,%3}, {%4,%5,%6,%7}, {%8,%9}, {%10,%10,%10,%10};"
        : "=f"(d[0]), "=f"(d[1]), "=f"(d[2]), "=f"(d[3])
        : "r"(a[0]), "r"(a[1]), "r"(a[2]), "r"(a[3]), "r"(b0), "r"(b1), "f"(0.f));
}
__device__ __forceinline__ void mma_e4(float* d, const uint32_t* a, uint32_t b0, uint32_t b1) {
    asm volatile(
        "mma.sync.aligned.m16n8k32.row.col.f32.e4m3.e4m3.f32 "
        "{%0,%1,%2,%3}, {%4,%5,%6,%7}, {%8,%9}, {%0,%1,%2,%3};"
        : "+f"(d[0]), "+f"(d[1]), "+f"(d[2]), "+f"(d[3])
        : "r"(a[0]), "r"(a[1]), "r"(a[2]), "r"(a[3]), "r"(b0), "r"(b1));
}
__device__ __forceinline__ uint32_t pack_h2(float lo, float hi) {
    __half2 t = __floats2half2_rn(lo, hi);
    return *reinterpret_cast<uint32_t*>(&t);
}
// pack 4 floats -> 4 e4m3 bytes (byte0 = f0)
__device__ __forceinline__ uint32_t pack_e4(float f0, float f1, float f2, float f3) {
    unsigned short lo, hi;
    asm("cvt.rn.satfinite.e4m3x2.f32 %0, %1, %2;" : "=h"(lo) : "f"(f1), "f"(f0));
    asm("cvt.rn.satfinite.e4m3x2.f32 %0, %1, %2;" : "=h"(hi) : "f"(f3), "f"(f2));
    return (uint32_t)lo | ((uint32_t)hi << 16);
}
__device__ __forceinline__ float h_round(float v) {      // fp16 round-trip
    return __half2float(__float2half_rn(v));
}

// ---------------- prep: warp per center ----------------
__global__ void prep_kernel(const float* __restrict__ centers,
                            const float* __restrict__ alphas,
                            const float* __restrict__ sigma) {
    const int m  = (blockIdx.x * blockDim.x + threadIdx.x) >> 5;
    const int ln = threadIdx.x & 31;                       // = dim k
    if (m >= M_CENT) return;
    const float g = sigma[0];
    const float c = sqrtf(1.44269504088896340736f / (g * g));
    float v = centers[m * D_DIM + ln] * c;
    // fp16 main part
    __half yh = __float2half_rn(v);
    float  yl = (v - __half2float(yh)) * 2048.0f;
    reinterpret_cast<__half*>(g_B + (size_t)m * 128)[ln] = yh;
    // fp8 block: offsets per layout
    const int q    = (ln & 15) >> 2;
    const int half = ln >> 4;
    const int bofs = 64 + 16 * q + 4 * half + (ln & 3);
    g_B[(size_t)m * 128 + bofs]     = (uint8_t)__nv_cvt_float_to_fp8(v,  __NV_SATFINITE, __NV_E4M3);
    g_B[(size_t)m * 128 + bofs + 8] = (uint8_t)__nv_cvt_float_to_fp8(yl, __NV_SATFINITE, __NV_E4M3);
    float y2 = v * v;
#pragma unroll
    for (int o = 16; o; o >>= 1) y2 += __shfl_xor_sync(0xFFFFFFFFu, y2, o);
    if (ln == 0) g_ya[m] = make_float2(-0.5f * y2, alphas[m]);
}

// ---------------- B tile loader ----------------
__device__ __forceinline__ void load_btile(uint32_t sb, int slot, int T, int tid) {
    const int split = T & (NSPLIT - 1);
    const uint8_t* src = g_B + (size_t)split * NTILE * 128;
    const uint32_t bd = sb + slot * SLOT;
#pragma unroll
    for (int i = 0; i < 4; i++) {
        int idx = tid + i * BLOCK;          // 0..1023 16B chunks (8 per center)
        int cc = idx >> 3, rr = idx & 7;
        cp16(bd + cc * BSTRIDE + rr * 16, src + idx * 16);
    }
    if (tid < 64) {
        const char* ys = reinterpret_cast<const char*>(g_ya + split * NTILE);
        cp16(bd + SLOT_B + tid * 16, ys + tid * 16);
    }
}

// ---------------- main kernel ----------------
__global__ void __launch_bounds__(BLOCK, 4)
rbf_main(const float* __restrict__ X,
         const float* __restrict__ sigma) {
    extern __shared__ char smem[];
    const uint32_t sb = smem_u32(smem);
    const int tid  = threadIdx.x;
    const int w    = tid >> 5;
    const int ln   = tid & 31;
    const int gID  = ln >> 2;
    const int qid  = ln & 3;
    const int row0 = w * 16 + gID;
    const int row1 = row0 + 8;

    const float g = __ldg(sigma);
    const float c = sqrtf(1.44269504088896340736f / (g * g));

    const int cta = blockIdx.x;
    const int loT = (int)(((long long)cta * TOTTILES) / NCTAS);
    const int hiT = (int)(((long long)(cta + 1) * TOTTILES) / NCTAS);
    const int n   = hiT - loT;

    load_btile(sb, 0, loT, tid);
    cp_commit();
    if (n > 1) load_btile(sb, 1, loT + 1, tid);
    cp_commit();

    const uint32_t blane = (uint32_t)((ln & 7) * BSTRIDE + (ln >> 3) * 16);

    uint32_t aH[2][4];   // fp16 A frags: kstep0, kstep1
    uint32_t aE[2][4];   // fp8  A frags: E1 (2048*xl), E2 (x)
    float ex0 = 1.f, ex1 = 1.f;
    int curRb = -1;

    for (int i = 0; i < n; i++) {
        const int T  = loT + i;
        const int rb = T >> 5;

        cp_wait<1>();
        __syncthreads();

        // ---- A fragments straight from global X ----
        if (rb != curRb) {
            curRb = rb;
            float s[2];
#pragma unroll
            for (int j = 0; j < 2; j++) {                 // j=0 -> row0, j=1 -> row1
                const int grow = rb * ROWS_CTA + (j ? row1 : row0);
                const float* rp = X + (size_t)grow * D_DIM;
                // fp16 set: dims 2q,2q+1 (+8,+16,+24)
                float2 u0 = *reinterpret_cast<const float2*>(rp + 2 * qid);
                float2 u1 = *reinterpret_cast<const float2*>(rp + 2 * qid + 8);
                float2 u2 = *reinterpret_cast<const float2*>(rp + 2 * qid + 16);
                float2 u3 = *reinterpret_cast<const float2*>(rp + 2 * qid + 24);
                u0.x *= c; u0.y *= c; u1.x *= c; u1.y *= c;
                u2.x *= c; u2.y *= c; u3.x *= c; u3.y *= c;
                s[j] = u0.x*u0.x + u0.y*u0.y + u1.x*u1.x + u1.y*u1.y
                     + u2.x*u2.x + u2.y*u2.y + u3.x*u3.x + u3.y*u3.y;
                aH[0][0 + j] = pack_h2(u0.x, u0.y);
                aH[0][2 + j] = pack_h2(u1.x, u1.y);
                aH[1][0 + j] = pack_h2(u2.x, u2.y);
                aH[1][2 + j] = pack_h2(u3.x, u3.y);
                // fp8 set: dims 4q..4q+3 and +16
                float4 w0 = *reinterpret_cast<const float4*>(rp + 4 * qid);
                float4 w1 = *reinterpret_cast<const float4*>(rp + 4 * qid + 16);
                w0.x *= c; w0.y *= c; w0.z *= c; w0.w *= c;
                w1.x *= c; w1.y *= c; w1.z *= c; w1.w *= c;
                aE[1][0 + j] = pack_e4(w0.x, w0.y, w0.z, w0.w);     // E2 A = x
                aE[1][2 + j] = pack_e4(w1.x, w1.y, w1.z, w1.w);
                aE[0][0 + j] = pack_e4(2048.f*(w0.x - h_round(w0.x)), 2048.f*(w0.y - h_round(w0.y)),
                                       2048.f*(w0.z - h_round(w0.z)), 2048.f*(w0.w - h_round(w0.w)));
                aE[0][2 + j] = pack_e4(2048.f*(w1.x - h_round(w1.x)), 2048.f*(w1.y - h_round(w1.y)),
                                       2048.f*(w1.z - h_round(w1.z)), 2048.f*(w1.w - h_round(w1.w)));
            }
            s[0] += __shfl_xor_sync(0xFFFFFFFFu, s[0], 1);
            s[0] += __shfl_xor_sync(0xFFFFFFFFu, s[0], 2);
            s[1] += __shfl_xor_sync(0xFFFFFFFFu, s[1], 1);
            s[1] += __shfl_xor_sync(0xFFFFFFFFu, s[1], 2);
            ex0 = ex2f(-0.5f * s[0]);
            ex1 = ex2f(-0.5f * s[1]);
        }

        // ---- consume tile i from slot i&1 ----
        const uint32_t Bs  = sb + (i & 1) * SLOT;
        const char*    yab = smem + (i & 1) * SLOT + SLOT_B;

        float acc0 = 0.f, acc1 = 0.f;
#pragma unroll
        for (int gi = 0; gi < NGRP; gi++) {
            // fp16 B frags (k0-31 of 8 centers)
            uint32_t p[4];
            ldmx4(p, Bs + gi * (8 * BSTRIDE) + blane);
            // fp8 B frags: one LDS.128 -> {b0_E1, b1_E1, b0_E2, b1_E2}
            const int bc = gi * 8 + (ln >> 2);
            uint4 e = *reinterpret_cast<const uint4*>(
                smem + (i & 1) * SLOT + bc * BSTRIDE + 64 + (ln & 3) * 16);
            float4 ya = *reinterpret_cast<const float4*>(yab + gi * 64 + qid * 16);

            float dT[4], dE[4];
            mma_f16_c(dT, aH[0], p[0], p[1], ya.x, ya.z, ya.x, ya.z);   // xh.yh k0-15 + bias
            mma_e4_z (dE, aE[0], e.x, e.y);                              // 2048*xl . y
            mma_f16  (dT, aH[1], p[2], p[3]);                            // xh.yh k16-31
            mma_e4   (dE, aE[1], e.z, e.w);                              // x . 2048*yl

            acc0 = fmaf(ex2f(fmaf(dE[0], INV_SCALE, dT[0])), ya.y, acc0);
            acc0 = fmaf(ex2f(fmaf(dE[1], INV_SCALE, dT[1])), ya.w, acc0);
            acc1 = fmaf(ex2f(fmaf(dE[2], INV_SCALE, dT[2])), ya.y, acc1);
            acc1 = fmaf(ex2f(fmaf(dE[3], INV_SCALE, dT[3])), ya.w, acc1);
        }

        __syncthreads();
        if (i + 2 < n) load_btile(sb, i & 1, T + 2, tid);
        cp_commit();

        acc0 += __shfl_xor_sync(0xFFFFFFFFu, acc0, 1);
        acc0 += __shfl_xor_sync(0xFFFFFFFFu, acc0, 2);
        acc1 += __shfl_xor_sync(0xFFFFFFFFu, acc1, 1);
        acc1 += __shfl_xor_sync(0xFFFFFFFFu, acc1, 2);
        if (qid == 0) {
            float* dst = g_part + (size_t)(T & (NSPLIT - 1)) * N_ROWS + rb * ROWS_CTA;
            dst[row0] = acc0 * ex0;
            dst[row1] = acc1 * ex1;
        }
    }
}

// ---------------- final reduce over 32 splits ----------------
__global__ void reduce_kernel(float* __restrict__ out) {
    const int nidx = blockIdx.x * blockDim.x + threadIdx.x;
    float s = 0.f;
#pragma unroll
    for (int i = 0; i < NSPLIT; i++) s += g_part[(size_t)i * N_ROWS + nidx];
    out[nidx] = s;
}

// ---------------- launch ----------------
extern "C" void kernel_launch(void* const* d_in, const int* in_sizes, int n_in,
                              void* d_out, int out_size) {
    const float* X       = (const float*)d_in[0];
    const float* centers = (const float*)d_in[1];
    const float* alphas  = (const float*)d_in[2];
    const float* sigma   = (const float*)d_in[3];
    float* out = (float*)d_out;

    cudaFuncSetAttribute(rbf_main, cudaFuncAttributeMaxDynamicSharedMemorySize, SMEM_TOT);

    prep_kernel<<<M_CENT / 8, 256>>>(centers, alphas, sigma);
    rbf_main<<<NCTAS, BLOCK, SMEM_TOT>>>(X, sigma);
    reduce_kernel<<<N_ROWS / 256, 256>>>(out);
}

// round 12
// speedup vs baseline: 1.4606x; 1.4606x over previous
#include <cuda_runtime.h>
#include <cuda_fp16.h>
#include <cstdint>

// ---------------- problem dims ----------------
#define N_ROWS 32768
#define M_CENT 4096
#define D_DIM  32

#define BLOCK     256                    // 8 warps, warp = 16 rows
#define ROWS_CTA  128
#define NTILE     128                    // centers per tile (= one split)
#define NSPLIT    32
#define NRB       (N_ROWS / ROWS_CTA)    // 256 row blocks
#define TOTTILES  (NRB * NSPLIT)         // 8192 work tiles
#define NCTAS     592                    // 148 SMs x 4 CTAs -> single wave
#define NGRP      (NTILE / 8)
#define BSTRIDE   144                    // 128B payload + 16B pad (conflict-free LDSM)

#define SLOT_B    (NTILE * BSTRIDE)      // 18432
#define SLOT_YA   (NTILE * 8)            // 1024
#define SLOT      (SLOT_B + SLOT_YA)     // 19456
#define SMEM_TOT  (2 * SLOT)             // 38912 -> 4 CTAs/SM

// ---------------- device scratch ----------------
// per center, 128 B: [0,64) fp16 yh ; [64,128) fp16 yl  (y = yh + yl, exact to 2^-23)
__device__ uint8_t g_B[M_CENT * 128];
__device__ float2  g_ya[M_CENT];            // { -0.5*||ys||^2 , alpha }
__device__ float   g_part[NSPLIT * N_ROWS];

// ---------------- helpers ----------------
__device__ __forceinline__ uint32_t smem_u32(const void* p) {
    uint32_t a;
    asm("{ .reg .u64 t; cvta.to.shared.u64 t, %1; cvt.u32.u64 %0, t; }" : "=r"(a) : "l"(p));
    return a;
}
__device__ __forceinline__ float ex2f(float x) {
    float r; asm("ex2.approx.f32 %0, %1;" : "=f"(r) : "f"(x)); return r;
}
__device__ __forceinline__ void cp16(uint32_t dst, const void* src) {
    asm volatile("cp.async.cg.shared.global [%0], [%1], 16;" :: "r"(dst), "l"(src));
}
__device__ __forceinline__ void cp_commit() {
    asm volatile("cp.async.commit_group;" ::: "memory");
}
template <int N>
__device__ __forceinline__ void cp_wait() {
    asm volatile("cp.async.wait_group %0;" :: "n"(N) : "memory");
}
__device__ __forceinline__ void ldmx4(uint32_t* r, uint32_t addr) {
    asm volatile("ldmatrix.sync.aligned.m8n8.x4.shared.b16 {%0,%1,%2,%3}, [%4];"
                 : "=r"(r[0]), "=r"(r[1]), "=r"(r[2]), "=r"(r[3]) : "r"(addr));
}
// fp16 m16n8k16: D = A*B + C  (separate C: free bias)
__device__ __forceinline__ void mma_f16_c(float* d, const uint32_t* a, uint32_t b0, uint32_t b1,
                                          float c0, float c1, float c2, float c3) {
    asm volatile(
        "mma.sync.aligned.m16n8k16.row.col.f32.f16.f16.f32 "
        "{%0,%1,%2,%3}, {%4,%5,%6,%7}, {%8,%9}, {%10,%11,%12,%13};"
        : "=f"(d[0]), "=f"(d[1]), "=f"(d[2]), "=f"(d[3])
        : "r"(a[0]), "r"(a[1]), "r"(a[2]), "r"(a[3]), "r"(b0), "r"(b1),
          "f"(c0), "f"(c1), "f"(c2), "f"(c3));
}
// fp16 m16n8k16: D = A*B + D
__device__ __forceinline__ void mma_f16(float* d, const uint32_t* a, uint32_t b0, uint32_t b1) {
    asm volatile(
        "mma.sync.aligned.m16n8k16.row.col.f32.f16.f16.f32 "
        "{%0,%1,%2,%3}, {%4,%5,%6,%7}, {%8,%9}, {%0,%1,%2,%3};"
        : "+f"(d[0]), "+f"(d[1]), "+f"(d[2]), "+f"(d[3])
        : "r"(a[0]), "r"(a[1]), "r"(a[2]), "r"(a[3]), "r"(b0), "r"(b1));
}
__device__ __forceinline__ uint32_t pack_h2(float lo, float hi) {
    __half2 t = __floats2half2_rn(lo, hi);
    return *reinterpret_cast<uint32_t*>(&t);
}

// ---------------- prep: warp per center, y -> fp16 pair split ----------------
__global__ void prep_kernel(const float* __restrict__ centers,
                            const float* __restrict__ alphas,
                            const float* __restrict__ sigma) {
    const int m  = (blockIdx.x * blockDim.x + threadIdx.x) >> 5;
    const int ln = threadIdx.x & 31;                       // = dim k
    if (m >= M_CENT) return;
    const float g = sigma[0];
    const float c = sqrtf(1.44269504088896340736f / (g * g));   // sqrt(log2e)/g
    float v = centers[m * D_DIM + ln] * c;
    __half yh = __float2half_rn(v);
    __half yl = __float2half_rn(v - __half2float(yh));     // residual fits fp16 (2^-23 total)
    reinterpret_cast<__half*>(g_B + (size_t)m * 128)[ln]      = yh;
    reinterpret_cast<__half*>(g_B + (size_t)m * 128 + 64)[ln] = yl;
    float y2 = v * v;
#pragma unroll
    for (int o = 16; o; o >>= 1) y2 += __shfl_xor_sync(0xFFFFFFFFu, y2, o);
    if (ln == 0) g_ya[m] = make_float2(-0.5f * y2, alphas[m]);
}

// ---------------- B tile loader: tile T -> ring slot ----------------
__device__ __forceinline__ void load_btile(uint32_t sb, int slot, int T, int tid) {
    const int split = T & (NSPLIT - 1);
    const uint8_t* src = g_B + (size_t)split * NTILE * 128;
    const uint32_t bd = sb + slot * SLOT;
#pragma unroll
    for (int i = 0; i < 4; i++) {
        int idx = tid + i * BLOCK;          // 0..1023 16B chunks (8 per center)
        int cc = idx >> 3, rr = idx & 7;
        cp16(bd + cc * BSTRIDE + rr * 16, src + idx * 16);
    }
    if (tid < 64) {
        const char* ys = reinterpret_cast<const char*>(g_ya + split * NTILE);
        cp16(bd + SLOT_B + tid * 16, ys + tid * 16);
    }
}

// ---------------- main kernel: persistent, 4 MMAs/group (K_eff = 64) ----------------
__global__ void __launch_bounds__(BLOCK, 4)
rbf_main(const float* __restrict__ X,
         const float* __restrict__ sigma) {
    extern __shared__ char smem[];
    const uint32_t sb = smem_u32(smem);
    const int tid  = threadIdx.x;
    const int w    = tid >> 5;
    const int ln   = tid & 31;
    const int gID  = ln >> 2;
    const int qid  = ln & 3;
    const int row0 = w * 16 + gID;      // CTA-local rows: row0, row0+8
    const int row1 = row0 + 8;

    const float g = __ldg(sigma);
    const float c = sqrtf(1.44269504088896340736f / (g * g));

    const int cta = blockIdx.x;
    const int loT = (int)(((long long)cta * TOTTILES) / NCTAS);
    const int hiT = (int)(((long long)(cta + 1) * TOTTILES) / NCTAS);
    const int n   = hiT - loT;

    load_btile(sb, 0, loT, tid);
    cp_commit();
    if (n > 1) load_btile(sb, 1, loT + 1, tid);
    cp_commit();

    const uint32_t blane = (uint32_t)((ln & 7) * BSTRIDE + (ln >> 3) * 16);

    uint32_t aH[2][4];   // fp16 A frags: kstep 0 (dims 0-15), kstep 1 (dims 16-31)
    float ex0 = 1.f, ex1 = 1.f;
    int curRb = -1;

    for (int i = 0; i < n; i++) {
        const int T  = loT + i;
        const int rb = T >> 5;

        cp_wait<1>();
        __syncthreads();

        // ---- A fragments straight from global X (fp16 single-rounded) ----
        if (rb != curRb) {
            curRb = rb;
            float s[2];
#pragma unroll
            for (int j = 0; j < 2; j++) {                 // j=0 -> row0, j=1 -> row1
                const int grow = rb * ROWS_CTA + (j ? row1 : row0);
                const float* rp = X + (size_t)grow * D_DIM;
                float2 u0 = *reinterpret_cast<const float2*>(rp + 2 * qid);
                float2 u1 = *reinterpret_cast<const float2*>(rp + 2 * qid + 8);
                float2 u2 = *reinterpret_cast<const float2*>(rp + 2 * qid + 16);
                float2 u3 = *reinterpret_cast<const float2*>(rp + 2 * qid + 24);
                u0.x *= c; u0.y *= c; u1.x *= c; u1.y *= c;
                u2.x *= c; u2.y *= c; u3.x *= c; u3.y *= c;
                s[j] = u0.x*u0.x + u0.y*u0.y + u1.x*u1.x + u1.y*u1.y
                     + u2.x*u2.x + u2.y*u2.y + u3.x*u3.x + u3.y*u3.y;
                aH[0][0 + j] = pack_h2(u0.x, u0.y);
                aH[0][2 + j] = pack_h2(u1.x, u1.y);
                aH[1][0 + j] = pack_h2(u2.x, u2.y);
                aH[1][2 + j] = pack_h2(u3.x, u3.y);
            }
            s[0] += __shfl_xor_sync(0xFFFFFFFFu, s[0], 1);
            s[0] += __shfl_xor_sync(0xFFFFFFFFu, s[0], 2);
            s[1] += __shfl_xor_sync(0xFFFFFFFFu, s[1], 1);
            s[1] += __shfl_xor_sync(0xFFFFFFFFu, s[1], 2);
            ex0 = ex2f(-0.5f * s[0]);
            ex1 = ex2f(-0.5f * s[1]);
        }

        // ---- consume tile i from slot i&1 ----
        const uint32_t Bb  = sb + (i & 1) * SLOT + blane;
        const char*    yab = smem + (i & 1) * SLOT + SLOT_B;

        float acc0 = 0.f, acc1 = 0.f;
#pragma unroll
        for (int gi = 0; gi < NGRP; gi++) {
            const uint32_t gb = Bb + gi * (8 * BSTRIDE);
            uint32_t p[4], r[4];
            ldmx4(p, gb);          // yh k0-31 (8 centers)
            ldmx4(r, gb + 64);     // yl k0-31
            float4 ya = *reinterpret_cast<const float4*>(yab + gi * 64 + qid * 16);

            float d[4];
            // xh.(yh+yl) = xh.y exactly; bias folded into first MMA's C
            mma_f16_c(d, aH[0], p[0], p[1], ya.x, ya.z, ya.x, ya.z);   // xh.yh k0-15 + bias
            mma_f16  (d, aH[1], p[2], p[3]);                            // xh.yh k16-31
            mma_f16  (d, aH[0], r[0], r[1]);                            // xh.yl k0-15
            mma_f16  (d, aH[1], r[2], r[3]);                            // xh.yl k16-31

            acc0 = fmaf(ex2f(d[0]), ya.y, acc0);
            acc0 = fmaf(ex2f(d[1]), ya.w, acc0);
            acc1 = fmaf(ex2f(d[2]), ya.y, acc1);
            acc1 = fmaf(ex2f(d[3]), ya.w, acc1);
        }

        __syncthreads();
        if (i + 2 < n) load_btile(sb, i & 1, T + 2, tid);
        cp_commit();

        acc0 += __shfl_xor_sync(0xFFFFFFFFu, acc0, 1);
        acc0 += __shfl_xor_sync(0xFFFFFFFFu, acc0, 2);
        acc1 += __shfl_xor_sync(0xFFFFFFFFu, acc1, 1);
        acc1 += __shfl_xor_sync(0xFFFFFFFFu, acc1, 2);
        if (qid == 0) {
            float* dst = g_part + (size_t)(T & (NSPLIT - 1)) * N_ROWS + rb * ROWS_CTA;
            dst[row0] = acc0 * ex0;
            dst[row1] = acc1 * ex1;
        }
    }
}

// ---------------- final reduce over 32 splits ----------------
__global__ void reduce_kernel(float* __restrict__ out) {
    const int nidx = blockIdx.x * blockDim.x + threadIdx.x;
    float s = 0.f;
#pragma unroll
    for (int i = 0; i < NSPLIT; i++) s += g_part[(size_t)i * N_ROWS + nidx];
    out[nidx] = s;
}

// ---------------- launch ----------------
extern "C" void kernel_launch(void* const* d_in, const int* in_sizes, int n_in,
                              void* d_out, int out_size) {
    const float* X       = (const float*)d_in[0];
    const float* centers = (const float*)d_in[1];
    const float* alphas  = (const float*)d_in[2];
    const float* sigma   = (const float*)d_in[3];
    float* out = (float*)d_out;

    cudaFuncSetAttribute(rbf_main, cudaFuncAttributeMaxDynamicSharedMemorySize, SMEM_TOT);

    prep_kernel<<<M_CENT / 8, 256>>>(centers, alphas, sigma);
    rbf_main<<<NCTAS, BLOCK, SMEM_TOT>>>(X, sigma);
    reduce_kernel<<<N_ROWS / 256, 256>>>(out);
}